// round 5
// baseline (speedup 1.0000x reference)
#include <cuda_runtime.h>

#define D 64
#define K 512
#define MT 128        // pixels per block
#define KT 128        // codes per chunk
#define PAD 132       // smem row stride (float4-aligned, conflict-free)
#define NPIX 131072   // 32*64*64
#define HW 4096       // 64*64
#define CHW 262144    // 64*4096
#define NBLK (NPIX / MT)

__device__ float g_wnorm[K];   // C_k = ||w_k||^2 (FULL, matches reference)
__device__ float g_bsum[NBLK];

// C_k = ||w_k||^2, sequential d-order fp32 accumulation
__global__ void wnorm_kernel(const float* __restrict__ w) {
    int k = threadIdx.x;  // 512 threads, 1 block
    float s = 0.f;
#pragma unroll
    for (int i = 0; i < D; i++) {
        float v = w[k * D + i];
        s = __fmaf_rn(v, v, s);
    }
    g_wnorm[k] = s;
}

extern __shared__ float smem[];

__global__ __launch_bounds__(256, 2) void vq_kernel(
    const float* __restrict__ x, const float* __restrict__ w,
    float* __restrict__ out) {
    float* xs = smem;            // [D][PAD] pixel tile, dim-major
    float* ws = smem + D * PAD;  // [D][PAD] code chunk, dim-major
    __shared__ int sidx[MT];
    __shared__ float lred[256];
    __shared__ float sA[MT];     // A_m = ||x_m||^2

    int tid = threadIdx.x;
    int p0 = blockIdx.x * MT;
    int b = p0 >> 12;            // 128 | 4096, so one batch per block
    int hw0 = p0 & (HW - 1);
    const float* xbase = x + (size_t)b * CHW + hw0;

    // Stage x tile: xs[d][m], coalesced global reads (m fast)
    for (int e = tid; e < D * MT; e += 256) {
        int d = e >> 7, m = e & 127;
        xs[d * PAD + m] = xbase[d * HW + m];
    }
    __syncthreads();

    // A_m = ||x_m||^2, sequential d-order fp32 (conflict-free: lanes -> consecutive m)
    if (tid < MT) {
        float s = 0.f;
#pragma unroll
        for (int d = 0; d < D; d++) {
            float v = xs[d * PAD + tid];
            s = __fmaf_rn(v, v, s);
        }
        sA[tid] = s;
    }
    __syncthreads();

    int tr = tid >> 4, tc = tid & 15;
    int m0 = tr * 8;

    float a[8];
#pragma unroll
    for (int i = 0; i < 8; i++) a[i] = sA[m0 + i];

    float minsc[8];
    int minidx[8];
#pragma unroll
    for (int i = 0; i < 8; i++) { minsc[i] = 3.4e38f; minidx[i] = 0; }

    for (int kc = 0; kc < K / KT; kc++) {
        __syncthreads();  // guard prior reads of ws
        // Stage w chunk transposed: ws[d][kk]
        for (int e = tid; e < D * KT; e += 256) {
            int d = e & 63, kk = e >> 6;
            ws[d * PAD + kk] = w[(kc * KT + kk) * D + d];
        }
        __syncthreads();

        float acc[8][8];
#pragma unroll
        for (int i = 0; i < 8; i++)
#pragma unroll
            for (int j = 0; j < 8; j++) acc[i][j] = 0.f;

#pragma unroll 8
        for (int d = 0; d < D; d++) {
            float4 xa = *reinterpret_cast<float4*>(&xs[d * PAD + m0]);
            float4 xb = *reinterpret_cast<float4*>(&xs[d * PAD + m0 + 4]);
            float4 wa = *reinterpret_cast<float4*>(&ws[d * PAD + tc * 8]);
            float4 wb = *reinterpret_cast<float4*>(&ws[d * PAD + tc * 8 + 4]);
            float xv[8] = {xa.x, xa.y, xa.z, xa.w, xb.x, xb.y, xb.z, xb.w};
            float wv[8] = {wa.x, wa.y, wa.z, wa.w, wb.x, wb.y, wb.z, wb.w};
#pragma unroll
            for (int i = 0; i < 8; i++)
#pragma unroll
                for (int j = 0; j < 8; j++)
                    acc[i][j] = __fmaf_rn(xv[i], wv[j], acc[i][j]);
        }

        // Reference-rounding argmin: dist = fl( fl(A - 2*dot) + C ), first-min on ties
#pragma unroll
        for (int j = 0; j < 8; j++) {
            int k = kc * KT + tc * 8 + j;
            float Ck = g_wnorm[k];
#pragma unroll
            for (int i = 0; i < 8; i++) {
                float t1 = __fmaf_rn(-2.0f, acc[i][j], a[i]);  // fl(A - 2B), 2B exact
                float sc = __fadd_rn(t1, Ck);                  // fl(t1 + C)
                if (sc < minsc[i]) { minsc[i] = sc; minidx[i] = k; }
            }
        }
    }

    __syncthreads();
    // Cross-thread argmin reduction (reuse ws region)
    float* rsc = ws;                                   // [MT][17]
    int* rix = reinterpret_cast<int*>(ws + MT * 17);   // [MT][17]
#pragma unroll
    for (int i = 0; i < 8; i++) {
        rsc[(m0 + i) * 17 + tc] = minsc[i];
        rix[(m0 + i) * 17 + tc] = minidx[i];
    }
    __syncthreads();
    if (tid < MT) {
        float best = rsc[tid * 17];
        int bidx = rix[tid * 17];
#pragma unroll
        for (int c = 1; c < 16; c++) {
            float sc = rsc[tid * 17 + c];
            int ix = rix[tid * 17 + c];
            if (sc < best || (sc == best && ix < bidx)) { best = sc; bidx = ix; }
        }
        sidx[tid] = bidx;
        out[p0 + tid] = (float)bidx;   // discrete_latent (as float)
    }
    __syncthreads();

    // Epilogue: straight-through forward fl(x + fl(q - x)) + loss partial.
    // Explicit roundings: must NOT fold x + (q - x) -> q (reference injects this noise).
    float lsum = 0.f;
    float* qout = out + NPIX + (size_t)b * CHW + hw0;
    for (int e = tid; e < D * MT; e += 256) {
        int d = e >> 7, m = e & 127;               // m fast => coalesced stores
        float wv = w[sidx[m] * D + d];             // scattered reads, L2-hot (codebook 128KB)
        float xv = xs[d * PAD + m];
        float df = __fsub_rn(wv, xv);
        lsum = __fmaf_rn(df, df, lsum);
        qout[d * HW + m] = __fadd_rn(xv, df);
    }
    lred[tid] = lsum;
    __syncthreads();
    for (int s = 128; s > 0; s >>= 1) {
        if (tid < s) lred[tid] += lred[tid + s];
        __syncthreads();
    }
    if (tid == 0) g_bsum[blockIdx.x] = lred[0];
}

// Deterministic fixed-order final loss reduce: loss = 1.25 * sum / (N*D)
__global__ void loss_kernel(float* __restrict__ out) {
    __shared__ float r[256];
    int tid = threadIdx.x;
    float s = 0.f;
    for (int i = tid; i < NBLK; i += 256) s += g_bsum[i];
    r[tid] = s;
    __syncthreads();
    for (int st = 128; st > 0; st >>= 1) {
        if (tid < st) r[tid] += r[tid + st];
        __syncthreads();
    }
    if (tid == 0) out[NPIX + (size_t)32 * CHW] = 1.25f * r[0] / 8388608.f;
}

extern "C" void kernel_launch(void* const* d_in, const int* in_sizes, int n_in,
                              void* d_out, int out_size) {
    const float* x = (const float*)d_in[0];   // [32, 64, 64, 64] NCHW fp32
    const float* w = (const float*)d_in[1];   // [512, 64] fp32
    float* out = (float*)d_out;

    size_t smem_bytes = (size_t)2 * D * PAD * sizeof(float);  // 67584 B
    cudaFuncSetAttribute(vq_kernel, cudaFuncAttributeMaxDynamicSharedMemorySize,
                         (int)smem_bytes);

    wnorm_kernel<<<1, K>>>(w);
    vq_kernel<<<NBLK, 256, smem_bytes>>>(x, w, out);
    loss_kernel<<<1, 256>>>(out);
}